// round 4
// baseline (speedup 1.0000x reference)
#include <cuda_runtime.h>

// Problem: B=2, C=32, H=80, W=240, D=64 (MAXDISP=192, D=192/3)
// out shape (B, 2C, D, H, W) fp32:
//   left  (c2 <  32): out = x[b,c2,h,w]        * (w >= d)
//   right (c2 >= 32): out = y[b,c2-32,h,w-d]   * (w >= d)
//
// 629 MB of stores, ~10 MB of (heavily reused, L2-resident) loads.
// Pure store-BW bound. Roofline ~100 us at ~6.3 TB/s.
//
// Launch shape: blockDim = (64, 4). threadIdx.x covers the 60 float4s of one
// output row (W=240 -> 60 float4, 4 idle lanes); (blockIdx.x*4 + threadIdx.y)
// selects the (b, c2, d, h) row. All branches warp-uniform; no 64-bit math.

#define BN 2
#define CN 32
#define HN 80
#define WN 240
#define DN 64
#define W4 (WN / 4)                       // 60 float4 per row
#define NROWS (BN * 2 * CN * DN * HN)     // 655,360 rows
#define ROWS_PER_BLOCK 4

__global__ __launch_bounds__(64 * ROWS_PER_BLOCK)
void cost_volume_kernel(const float* __restrict__ x,
                        const float* __restrict__ y,
                        float* __restrict__ out)
{
    int w4 = threadIdx.x;                 // 0..63, active 0..59
    int row = blockIdx.x * ROWS_PER_BLOCK + threadIdx.y;
    if (w4 >= W4) return;                 // NROWS divisible by ROWS_PER_BLOCK

    // row -> (b, c2, d, h), h fastest
    int h  = row % HN;  int t = row / HN;
    int d  = t & (DN - 1);  t >>= 6;      // d = t % 64
    int c2 = t & (2 * CN - 1);            // c2 = t % 64
    int b  = t >> 6;

    int w0 = w4 * 4;
    float4 v;

    if (c2 < CN) {
        // left: aligned float4 load from x, mask lanes where w < d
        const float4* xr = reinterpret_cast<const float4*>(
            x + (((b * CN + c2) * HN + h) * WN));
        v = __ldg(xr + w4);
        if (w0 < d) {                     // warp-uniform within a row
            v.x = (w0     >= d) ? v.x : 0.0f;
            v.y = (w0 + 1 >= d) ? v.y : 0.0f;
            v.z = (w0 + 2 >= d) ? v.z : 0.0f;
            v.w = (w0 + 3 >= d) ? v.w : 0.0f;
        }
    } else {
        // right: y[b, c, h, w - d] * (w >= d); scalar loads (misaligned by d),
        // but y is fully L2-resident (4.9 MB, 64x reuse) so latency is hidden.
        int c = c2 - CN;
        const float* yr = y + (((b * CN + c) * HN + h) * WN);
        v.x = (w0     >= d) ? __ldg(yr + (w0     - d)) : 0.0f;
        v.y = (w0 + 1 >= d) ? __ldg(yr + (w0 + 1 - d)) : 0.0f;
        v.z = (w0 + 2 >= d) ? __ldg(yr + (w0 + 2 - d)) : 0.0f;
        v.w = (w0 + 3 >= d) ? __ldg(yr + (w0 + 3 - d)) : 0.0f;
    }

    // Streaming store: 629 MB output must not evict the L2-resident inputs.
    int out_idx = row * W4 + w4;          // max 39,321,599 < 2^31
    __stcs(reinterpret_cast<float4*>(out) + out_idx, v);
}

extern "C" void kernel_launch(void* const* d_in, const int* in_sizes, int n_in,
                              void* d_out, int out_size)
{
    const float* x = (const float*)d_in[0];
    const float* y = (const float*)d_in[1];
    float* out = (float*)d_out;

    dim3 block(64, ROWS_PER_BLOCK);
    dim3 grid(NROWS / ROWS_PER_BLOCK);    // 163,840 blocks
    cost_volume_kernel<<<grid, block>>>(x, y, out);
}

// round 6
// speedup vs baseline: 1.0771x; 1.0771x over previous
#include <cuda_runtime.h>

// Problem: B=2, C=32, H=80, W=240, D=64 (MAXDISP=192, D=192/3)
// out shape (B, 2C, D, H, W) fp32:
//   left  (c2 <  32): out = x[b,c2,h,w]        * (w >= d)
//   right (c2 >= 32): out = y[b,c2-32,h,w-d]   * (w >= d)
//
// 629 MB of stores, ~10 MB of (heavily reused, L2-resident) loads.
// Pure store-BW bound. Roofline ~100 us.
//
// Flat 1D mapping: one thread per output float4. TOTAL4 = 39,321,600 is
// divisible by 256 -> every warp fully active, every STG.128 wavefront 100%
// full (R4 profile showed the (64,4) layout wasted 4/64 lanes per row on the
// store path). Rows are 60 float4 wide, so a warp spans at most 2 rows;
// c2 / d / b are warp-uniform for the vast majority of warps.

#define BN 2
#define CN 32
#define HN 80
#define WN 240
#define DN 64
#define W4 (WN / 4)                               // 60 float4 per row
#define TOTAL4 (BN * 2 * CN * DN * HN * W4)       // 39,321,600 = 153600 * 256

__global__ __launch_bounds__(256)
void cost_volume_kernel(const float* __restrict__ x,
                        const float* __restrict__ y,
                        float* __restrict__ out)
{
    unsigned int i = blockIdx.x * 256u + threadIdx.x;   // no bounds check needed

    // i -> (row, w4); row -> (b, c2, d, h), h fastest
    unsigned int row = i / W4;                    // magic-number div
    unsigned int w4  = i - row * W4;
    unsigned int h   = row % HN;                  // magic-number mod
    unsigned int t   = row / HN;
    unsigned int d   = t & (DN - 1);   t >>= 6;
    unsigned int c2  = t & (2 * CN - 1);
    unsigned int b   = t >> 6;

    int w0 = (int)(w4 * 4);
    int di = (int)d;
    float4 v;

    if (c2 < CN) {
        // left: aligned float4 load from x, mask lanes where w < d
        const float4* xr = reinterpret_cast<const float4*>(
            x + (((b * CN + c2) * HN + h) * WN));
        v = __ldg(xr + w4);
        if (w0 < di) {
            v.x = (w0     >= di) ? v.x : 0.0f;
            v.y = (w0 + 1 >= di) ? v.y : 0.0f;
            v.z = (w0 + 2 >= di) ? v.z : 0.0f;
            v.w = (w0 + 3 >= di) ? v.w : 0.0f;
        }
    } else {
        // right: y[b, c, h, w - d] * (w >= d); scalar loads (misaligned by d),
        // y is fully L2-resident (4.9 MB, 64x reuse) so latency is hidden.
        unsigned int c = c2 - CN;
        const float* yr = y + (((b * CN + c) * HN + h) * WN);
        v.x = (w0     >= di) ? __ldg(yr + (w0     - di)) : 0.0f;
        v.y = (w0 + 1 >= di) ? __ldg(yr + (w0 + 1 - di)) : 0.0f;
        v.z = (w0 + 2 >= di) ? __ldg(yr + (w0 + 2 - di)) : 0.0f;
        v.w = (w0 + 3 >= di) ? __ldg(yr + (w0 + 3 - di)) : 0.0f;
    }

    // Streaming store: 629 MB output must not evict the L2-resident inputs.
    __stcs(reinterpret_cast<float4*>(out) + i, v);
}

extern "C" void kernel_launch(void* const* d_in, const int* in_sizes, int n_in,
                              void* d_out, int out_size)
{
    const float* x = (const float*)d_in[0];
    const float* y = (const float*)d_in[1];
    float* out = (float*)d_out;

    cost_volume_kernel<<<TOTAL4 / 256, 256>>>(x, y, out);
}

// round 7
// speedup vs baseline: 1.1410x; 1.0594x over previous
#include <cuda_runtime.h>

// Problem: B=2, C=32, H=80, W=240, D=64 (MAXDISP=192, D=192/3)
// out shape (B, 2C, D, H, W) fp32:
//   left  (c2 <  32): out = x[b,c2,h,w]        * (w >= d)
//   right (c2 >= 32): out = y[b,c2-32,h,w-d]   * (w >= d)
//
// 629 MB of stores, ~10 MB of (heavily reused, L2-resident) loads.
// Pure store-BW bound; measured 6.26 TB/s write stream at R6 (100.5 us).
//
// This round: 2 float4s per thread (j and j+256) -> 2 independent
// load->store chains per thread (store MLP=2), half the blocks, zero tail.
// All stores remain perfectly coalesced; __stcs keeps the 629 MB output
// stream from evicting the 64x-reused inputs out of L2.

#define BN 2
#define CN 32
#define HN 80
#define WN 240
#define DN 64
#define W4 (WN / 4)                               // 60 float4 per row
#define TOTAL4 (BN * 2 * CN * DN * HN * W4)       // 39,321,600 = 76800 * 512

__device__ __forceinline__ float4 compute_elem(
    const float* __restrict__ x, const float* __restrict__ y, unsigned int i)
{
    // i -> (row, w4); row -> (b, c2, d, h), h fastest
    unsigned int row = i / W4;                    // magic-number div
    unsigned int w4  = i - row * W4;
    unsigned int h   = row % HN;                  // magic-number mod
    unsigned int t   = row / HN;
    unsigned int d   = t & (DN - 1);   t >>= 6;
    unsigned int c2  = t & (2 * CN - 1);
    unsigned int b   = t >> 6;

    int w0 = (int)(w4 * 4);
    int di = (int)d;
    float4 v;

    if (c2 < CN) {
        // left: aligned float4 load from x, mask lanes where w < d
        const float4* xr = reinterpret_cast<const float4*>(
            x + (((b * CN + c2) * HN + h) * WN));
        v = __ldg(xr + w4);
        if (w0 < di) {
            v.x = (w0     >= di) ? v.x : 0.0f;
            v.y = (w0 + 1 >= di) ? v.y : 0.0f;
            v.z = (w0 + 2 >= di) ? v.z : 0.0f;
            v.w = (w0 + 3 >= di) ? v.w : 0.0f;
        }
    } else {
        // right: y[b, c, h, w - d]; scalar loads (misaligned by d), y is
        // fully L2-resident (4.9 MB, 64x reuse) so latency is hidden.
        unsigned int c = c2 - CN;
        const float* yr = y + (((b * CN + c) * HN + h) * WN);
        v.x = (w0     >= di) ? __ldg(yr + (w0     - di)) : 0.0f;
        v.y = (w0 + 1 >= di) ? __ldg(yr + (w0 + 1 - di)) : 0.0f;
        v.z = (w0 + 2 >= di) ? __ldg(yr + (w0 + 2 - di)) : 0.0f;
        v.w = (w0 + 3 >= di) ? __ldg(yr + (w0 + 3 - di)) : 0.0f;
    }
    return v;
}

__global__ __launch_bounds__(256)
void cost_volume_kernel(const float* __restrict__ x,
                        const float* __restrict__ y,
                        float* __restrict__ out)
{
    unsigned int j0 = blockIdx.x * 512u + threadIdx.x;
    unsigned int j1 = j0 + 256u;

    float4 v0 = compute_elem(x, y, j0);
    float4 v1 = compute_elem(x, y, j1);

    float4* o = reinterpret_cast<float4*>(out);
    __stcs(o + j0, v0);
    __stcs(o + j1, v1);
}

extern "C" void kernel_launch(void* const* d_in, const int* in_sizes, int n_in,
                              void* d_out, int out_size)
{
    const float* x = (const float*)d_in[0];
    const float* y = (const float*)d_in[1];
    float* out = (float*)d_out;

    cost_volume_kernel<<<TOTAL4 / 512, 256>>>(x, y, out);
}

// round 8
// speedup vs baseline: 1.1464x; 1.0047x over previous
#include <cuda_runtime.h>

// Problem: B=2, C=32, H=80, W=240, D=64 (MAXDISP=192, D=192/3)
// out shape (B, 2C, D, H, W) fp32:
//   left  (c2 <  32): out = x[b,c2,h,w]        * (w >= d)
//   right (c2 >= 32): out = y[b,c2-32,h,w-d]   * (w >= d)
//
// 629 MB of stores, ~10 MB of (heavily reused, L2-resident) loads.
// Pure store-BW bound; R7 measured 6.63 TB/s write stream (94.8 us) with
// 2 stores/thread. This round: 4 float4s per thread (j, j+256, j+512, j+768)
// -> 4 independent load->store chains (store MLP=4), blocks 76800->38400,
// zero tail. All stores perfectly coalesced; __stcs keeps the 629 MB output
// stream from evicting the 64x-reused inputs out of L2.

#define BN 2
#define CN 32
#define HN 80
#define WN 240
#define DN 64
#define W4 (WN / 4)                               // 60 float4 per row
#define TOTAL4 (BN * 2 * CN * DN * HN * W4)       // 39,321,600 = 38400 * 1024

__device__ __forceinline__ float4 compute_elem(
    const float* __restrict__ x, const float* __restrict__ y, unsigned int i)
{
    // i -> (row, w4); row -> (b, c2, d, h), h fastest
    unsigned int row = i / W4;                    // magic-number div
    unsigned int w4  = i - row * W4;
    unsigned int h   = row % HN;                  // magic-number mod
    unsigned int t   = row / HN;
    unsigned int d   = t & (DN - 1);   t >>= 6;
    unsigned int c2  = t & (2 * CN - 1);
    unsigned int b   = t >> 6;

    int w0 = (int)(w4 * 4);
    int di = (int)d;
    float4 v;

    if (c2 < CN) {
        // left: aligned float4 load from x, mask lanes where w < d
        const float4* xr = reinterpret_cast<const float4*>(
            x + (((b * CN + c2) * HN + h) * WN));
        v = __ldg(xr + w4);
        if (w0 < di) {
            v.x = (w0     >= di) ? v.x : 0.0f;
            v.y = (w0 + 1 >= di) ? v.y : 0.0f;
            v.z = (w0 + 2 >= di) ? v.z : 0.0f;
            v.w = (w0 + 3 >= di) ? v.w : 0.0f;
        }
    } else {
        // right: y[b, c, h, w - d]; scalar loads (misaligned by d), y is
        // fully L2-resident (4.9 MB, 64x reuse) so latency is hidden.
        unsigned int c = c2 - CN;
        const float* yr = y + (((b * CN + c) * HN + h) * WN);
        v.x = (w0     >= di) ? __ldg(yr + (w0     - di)) : 0.0f;
        v.y = (w0 + 1 >= di) ? __ldg(yr + (w0 + 1 - di)) : 0.0f;
        v.z = (w0 + 2 >= di) ? __ldg(yr + (w0 + 2 - di)) : 0.0f;
        v.w = (w0 + 3 >= di) ? __ldg(yr + (w0 + 3 - di)) : 0.0f;
    }
    return v;
}

__global__ __launch_bounds__(256)
void cost_volume_kernel(const float* __restrict__ x,
                        const float* __restrict__ y,
                        float* __restrict__ out)
{
    unsigned int j0 = blockIdx.x * 1024u + threadIdx.x;

    float4 v0 = compute_elem(x, y, j0);
    float4 v1 = compute_elem(x, y, j0 + 256u);
    float4 v2 = compute_elem(x, y, j0 + 512u);
    float4 v3 = compute_elem(x, y, j0 + 768u);

    float4* o = reinterpret_cast<float4*>(out);
    __stcs(o + j0,        v0);
    __stcs(o + j0 + 256u, v1);
    __stcs(o + j0 + 512u, v2);
    __stcs(o + j0 + 768u, v3);
}

extern "C" void kernel_launch(void* const* d_in, const int* in_sizes, int n_in,
                              void* d_out, int out_size)
{
    const float* x = (const float*)d_in[0];
    const float* y = (const float*)d_in[1];
    float* out = (float*)d_out;

    cost_volume_kernel<<<TOTAL4 / 1024, 256>>>(x, y, out);
}